// round 5
// baseline (speedup 1.0000x reference)
#include <cuda_runtime.h>

#define N 256
#define NPH (N/2 + 2)          // 130 phase layers
#define NSTAGES (N/2)          // 128 ADA stages; stages 1..127 followed by crossing

// Precomputed exp(i*theta) for all layers: [130][256] complex interleaved.
__device__ float2 g_phases[NPH * N];

__global__ void phase_kernel(const float* __restrict__ thetas, int n) {
    int i = blockIdx.x * blockDim.x + threadIdx.x;
    if (i < n) {
        float s, c;
        sincosf(thetas[i], &s, &c);
        g_phases[i] = make_float2(c, s);
    }
}

// One block = one column of the matrix. Thread t owns rows (2t, 2t+1) in
// registers. MMI / phase / MMI are row-pair-local; the crossing exchanges one
// complex value with each neighboring thread via ping-pong shared buffers.
//
// Output modes:
//   0: interleaved complex row-major: out2[row*N+col] = (re, im)
//   1: planar float32 [2][N][N]
//   2: interleaved complex TRANSPOSED: out2[col*N+row]
//   3: REAL PART only, row-major float32 [N][N]
__global__ __launch_bounds__(128) void mesh_kernel(float* __restrict__ out, int mode) {
    const int t   = threadIdx.x;
    const int col = blockIdx.x;

    // MMI constants: A = sqrt(1-IL)*[[T, iR],[iR, T]]
    const float AT = sqrtf(0.98f * 0.505f);   // sqrt(1-IL_MMI)*sqrt((1+IMB)/2)
    const float AR = sqrtf(0.98f * 0.495f);   // sqrt(1-IL_MMI)*sqrt((1-IMB)/2)
    // Crossing constants
    const float CS   = sqrtf(0.98f * 0.01f);  // sqrt(1-IL_CR)*sqrt(CT)
    const float CN   = sqrtf(0.98f * 0.99f);  // sqrt(1-IL_CR)*sqrt(1-CT)
    const float THRU = CN;                    // pass-through rows 0, N-1

    // Ping-pong exchange buffers: X[t] = row 2t, Y[t] = row 2t+1
    __shared__ float2 Xs[2][128];
    __shared__ float2 Ys[2][128];

    // Initial state: column col of diag(exp(i*theta[0])) -> e_col * ph0[col]
    float2 x = make_float2(0.f, 0.f);
    float2 y = make_float2(0.f, 0.f);
    if (t == (col >> 1)) {
        float2 p = g_phases[col];
        if (col & 1) y = p; else x = p;
    }

    #pragma unroll 1
    for (int s = 1; s <= NSTAGES; s++) {
        // phases for rows 2t, 2t+1 of layer s (16B aligned, coalesced)
        float4 ph = *reinterpret_cast<const float4*>(&g_phases[s * N + 2 * t]);

        // --- MMI ---
        float x1r = AT * x.x - AR * y.y;
        float x1i = AT * x.y + AR * y.x;
        float y1r = AT * y.x - AR * x.y;
        float y1i = AT * y.y + AR * x.x;
        // --- phase diag: x2 = p0*x1, y2 = p1*y1 ---
        float x2r = ph.x * x1r - ph.y * x1i;
        float x2i = ph.x * x1i + ph.y * x1r;
        float y2r = ph.z * y1r - ph.w * y1i;
        float y2i = ph.z * y1i + ph.w * y1r;
        // --- MMI ---
        x.x = AT * x2r - AR * y2i;
        x.y = AT * x2i + AR * y2r;
        y.x = AT * y2r - AR * x2i;
        y.y = AT * y2i + AR * x2r;

        if (s < NSTAGES) {
            // --- crossing: pairs (2t+1, 2t+2) = (y_t, x_{t+1}) ---
            const int b = s & 1;
            Xs[b][t] = x;
            Ys[b][t] = y;
            __syncthreads();

            float2 nx, ny;
            if (t < 127) {
                float2 xn = Xs[b][t + 1];
                ny.x = CS * y.x - CN * xn.y;   // CS*y + i*CN*x_{t+1}
                ny.y = CS * y.y + CN * xn.x;
            } else {
                ny.x = THRU * y.x;             // row N-1 pass-through
                ny.y = THRU * y.y;
            }
            if (t > 0) {
                float2 yp = Ys[b][t - 1];
                nx.x = CS * x.x - CN * yp.y;   // i*CN*y_{t-1} + CS*x
                nx.y = CS * x.y + CN * yp.x;
            } else {
                nx.x = THRU * x.x;             // row 0 pass-through
                nx.y = THRU * x.y;
            }
            x = nx;
            y = ny;
        }
    }

    // Final phase layer: row r scaled by exp(i*theta[129][r])
    {
        float4 ph = *reinterpret_cast<const float4*>(&g_phases[(NPH - 1) * N + 2 * t]);
        float xr = ph.x * x.x - ph.y * x.y;
        float xi = ph.x * x.y + ph.y * x.x;
        float yr = ph.z * y.x - ph.w * y.y;
        float yi = ph.z * y.y + ph.w * y.x;
        x = make_float2(xr, xi);
        y = make_float2(yr, yi);
    }

    const int r0 = 2 * t;       // row of x
    const int r1 = 2 * t + 1;   // row of y

    if (mode == 3) {
        // real part only, row-major [N][N]
        out[r0 * N + col] = x.x;
        out[r1 * N + col] = y.x;
    } else if (mode == 1) {
        // planar float32 [2][N][N]
        out[r0 * N + col]         = x.x;
        out[N * N + r0 * N + col] = x.y;
        out[r1 * N + col]         = y.x;
        out[N * N + r1 * N + col] = y.y;
    } else if (mode == 2) {
        // interleaved complex, transposed
        float2* o = reinterpret_cast<float2*>(out);
        o[col * N + r0] = x;
        o[col * N + r1] = y;
    } else {
        // interleaved complex, row-major
        float2* o = reinterpret_cast<float2*>(out);
        o[r0 * N + col] = x;
        o[r1 * N + col] = y;
    }
}

extern "C" void kernel_launch(void* const* d_in, const int* in_sizes, int n_in,
                              void* d_out, int out_size) {
    const float* thetas = (const float*)d_in[0];
    int n = in_sizes[0];  // 130 * 256 = 33280

    // Fresh-hypothesis dispatch (see round log):
    //   out_size == N*N     -> real part only (complex->float32 astype cast)
    //   out_size == 2*N*N   -> transposed interleaved (untested at this size)
    //   otherwise           -> interleaved row-major
    int mode;
    if (out_size == N * N)          mode = 3;
    else if (out_size == 2 * N * N) mode = 2;
    else                            mode = 0;

    phase_kernel<<<(n + 255) / 256, 256>>>(thetas, n);
    mesh_kernel<<<N, 128>>>((float*)d_out, mode);
}